// round 1
// baseline (speedup 1.0000x reference)
#include <cuda_runtime.h>
#include <math.h>

// Problem constants (from reference setup_inputs)
#define BB 32
#define NN 512
#define DD 1024
#define HH 512
#define MM (BB*NN)   // 16384 rows

// GEMM tiling
#define BM 128
#define BN 128
#define BK 16
#define TM 8
#define TN 8

// Scratch (allocation-free rule: __device__ globals)
__device__ float g_yacc[MM];
__device__ float g_qacc[MM];

__device__ __forceinline__ float ssp(float x) {
    // shifted softplus: softplus(x) - ln2
    float sp = (x > 20.0f) ? x : log1pf(__expf(x));
    return sp - 0.6931471805599453f;
}

__global__ void init_kernel(float* __restrict__ out) {
    int i = blockIdx.x * blockDim.x + threadIdx.x;
    if (i < MM) { g_yacc[i] = 0.0f; g_qacc[i] = 0.0f; }
    if (i < BB) out[i] = 0.0f;
}

// Fused: Z = rep @ [W1 | Wc1]  (M x 1024), then per element ssp(z+bias)*w2,
// row-reduced and atomically accumulated into g_yacc (half 0) / g_qacc (half 1).
__global__ __launch_bounds__(256)
void mlp_kernel(const float* __restrict__ rep,
                const float* __restrict__ W1,  const float* __restrict__ b1,
                const float* __restrict__ W2,
                const float* __restrict__ Wc1, const float* __restrict__ bc1,
                const float* __restrict__ Wc2)
{
    __shared__ float As[BK][BM + 4];
    __shared__ float Bs[BK][BN];
    __shared__ float rowsum[BM];

    const int tid = threadIdx.x;
    const int tx = tid & 15;          // 0..15 (cols)
    const int ty = tid >> 4;          // 0..15 (rows)

    const int mBase  = blockIdx.y * BM;
    const int half   = blockIdx.x >> 2;              // 0 -> (W1,b1,W2), 1 -> (Wc1,bc1,Wc2)
    const int nBaseH = (blockIdx.x & 3) * BN;        // column base within the half

    const float* __restrict__ W    = half ? Wc1 : W1;
    const float* __restrict__ bias = half ? bc1 : b1;
    const float* __restrict__ w2   = half ? Wc2 : W2;

    float acc[TM][TN] = {};

    for (int k0 = 0; k0 < DD; k0 += BK) {
        // Load A tile (BM x BK) transposed into As[k][m]; 512 float4, 2/thread
        #pragma unroll
        for (int l = 0; l < 2; l++) {
            int f   = tid + l * 256;
            int row = f >> 2;
            int c4  = (f & 3) << 2;
            float4 v = *(const float4*)&rep[(mBase + row) * DD + k0 + c4];
            As[c4 + 0][row] = v.x;
            As[c4 + 1][row] = v.y;
            As[c4 + 2][row] = v.z;
            As[c4 + 3][row] = v.w;
        }
        // Load B tile (BK x BN); 512 float4, 2/thread
        #pragma unroll
        for (int l = 0; l < 2; l++) {
            int f   = tid + l * 256;
            int row = f >> 5;
            int c4  = (f & 31) << 2;
            *(float4*)&Bs[row][c4] =
                *(const float4*)&W[(k0 + row) * HH + nBaseH + c4];
        }
        __syncthreads();

        #pragma unroll
        for (int k = 0; k < BK; k++) {
            float a[TM], bf[TN];
            #pragma unroll
            for (int i = 0; i < TM; i++) a[i] = As[k][ty * TM + i];
            #pragma unroll
            for (int j = 0; j < TN; j++) bf[j] = Bs[k][tx * TN + j];
            #pragma unroll
            for (int i = 0; i < TM; i++)
                #pragma unroll
                for (int j = 0; j < TN; j++)
                    acc[i][j] = fmaf(a[i], bf[j], acc[i][j]);
        }
        __syncthreads();
    }

    // Epilogue: ssp(z + bias) * w2, reduce over the 128 cols of this CTA.
    float bv[TN], wv[TN];
    #pragma unroll
    for (int j = 0; j < TN; j++) {
        int col = nBaseH + tx * TN + j;
        bv[j] = bias[col];
        wv[j] = w2[col];
    }

    float p[TM];
    #pragma unroll
    for (int i = 0; i < TM; i++) {
        float s = 0.0f;
        #pragma unroll
        for (int j = 0; j < TN; j++)
            s += ssp(acc[i][j] + bv[j]) * wv[j];
        p[i] = s;
    }

    if (tid < BM) rowsum[tid] = 0.0f;
    __syncthreads();
    #pragma unroll
    for (int i = 0; i < TM; i++)
        atomicAdd(&rowsum[ty * TM + i], p[i]);
    __syncthreads();

    if (tid < BM) {
        float* dst = half ? g_qacc : g_yacc;
        atomicAdd(&dst[mBase + tid], rowsum[tid]);
    }
}

// Coulomb pair sum + masked atom pool. One block per (batch, 64-row chunk).
#define CHUNK 64
__global__ __launch_bounds__(256)
void coulomb_kernel(const float* __restrict__ R,
                    const float* __restrict__ mask,
                    const float* __restrict__ b2p,
                    const float* __restrict__ bc2p,
                    float* __restrict__ out)
{
    const int nchunks = NN / CHUNK;            // 8
    const int b     = blockIdx.x / nchunks;
    const int chunk = blockIdx.x % nchunks;
    const int tid   = threadIdx.x;

    __shared__ float qx[NN], Rx[NN], Ry[NN], Rz[NN];
    __shared__ float red[8];

    const float b2v  = b2p[0];
    const float bc2v = bc2p[0];

    for (int n = tid; n < NN; n += 256) {
        float mk = mask[b * NN + n];
        qx[n] = (g_qacc[b * NN + n] + bc2v) * mk;   // masked charge
        const float* r = &R[(b * NN + n) * 3];
        Rx[n] = r[0]; Ry[n] = r[1]; Rz[n] = r[2];
    }
    __syncthreads();

    float acc = 0.0f;
    const int i0 = chunk * CHUNK;
    for (int idx = tid; idx < CHUNK * NN; idx += 256) {
        int i = i0 + (idx >> 9);        // idx / NN
        int j = idx & (NN - 1);         // idx % NN
        if (i == j) continue;
        float dx = Rx[i] - Rx[j];
        float dy = Ry[i] - Ry[j];
        float dz = Rz[i] - Rz[j];
        float d2 = dx * dx + dy * dy + dz * dz;
        float d  = (d2 > 0.0f) ? sqrtf(d2) : 0.0f;
        float t  = 1e-5f + d;
        acc += (qx[i] * qx[j]) / (t * t);
    }

    // pool the atomwise-energy rows of this chunk
    for (int i = i0 + tid; i < i0 + CHUNK; i += 256) {
        acc += (g_yacc[b * NN + i] + b2v) * mask[b * NN + i];
    }

    // block reduce
    #pragma unroll
    for (int off = 16; off > 0; off >>= 1)
        acc += __shfl_down_sync(0xFFFFFFFF, acc, off);
    if ((tid & 31) == 0) red[tid >> 5] = acc;
    __syncthreads();
    if (tid < 8) {
        float v = red[tid];
        #pragma unroll
        for (int off = 4; off > 0; off >>= 1)
            v += __shfl_down_sync(0xFF, v, off);
        if (tid == 0) atomicAdd(&out[b], v);
    }
}

extern "C" void kernel_launch(void* const* d_in, const int* in_sizes, int n_in,
                              void* d_out, int out_size) {
    const float* rep  = (const float*)d_in[0];
    const float* R    = (const float*)d_in[1];
    const float* mask = (const float*)d_in[2];
    const float* W1   = (const float*)d_in[3];
    const float* b1   = (const float*)d_in[4];
    const float* W2   = (const float*)d_in[5];
    const float* b2   = (const float*)d_in[6];
    const float* Wc1  = (const float*)d_in[7];
    const float* bc1  = (const float*)d_in[8];
    const float* Wc2  = (const float*)d_in[9];
    const float* bc2  = (const float*)d_in[10];
    float* out = (float*)d_out;

    init_kernel<<<(MM + 255) / 256, 256>>>(out);
    mlp_kernel<<<dim3(8, MM / BM), 256>>>(rep, W1, b1, W2, Wc1, bc1, Wc2);
    coulomb_kernel<<<BB * (NN / CHUNK), 256>>>(R, mask, b2, bc2, out);
}